// round 17
// baseline (speedup 1.0000x reference)
#include <cuda_runtime.h>
#include <cstddef>
#include <cstdint>

// RoutingByAgreement: x[B,64,64] f32 -> v[B,64] f32, 3 iterations.
// FOUR-WARP CTA (128 threads) per batch, 7 CTAs/SM -> 28 warps/SM,
// 7 independent batch streams. Warp w owns rows 16w..16w+15; lane l owns
// cols 2l,2l+1: float2 xc[16] (32 regs).
//   s-phase:   per-warp partial (in-lane) -> sp[4][32] smem -> every warp
//              redundantly combines to full s and squash scale (shuffle-only).
//   agreement: intra-warp 16-row butterfly (16 shfl), row = 16w+bitrev4(l).
//   softmax:   se[64] strip; Z = se[l]+se[l+32] + 5-shfl.
// 6 __syncthreads per batch (incl. batch-end WAR fence for sp).

#define FULLMASK 0xffffffffu

static __device__ __forceinline__ float frcp(float x) {
    float r; asm("rcp.approx.f32 %0, %1;" : "=f"(r) : "f"(x)); return r;
}
static __device__ __forceinline__ float frsq(float x) {
    float r; asm("rsqrt.approx.f32 %0, %1;" : "=f"(r) : "f"(x)); return r;
}

__global__ void __launch_bounds__(128, 7)
routing_kernel(const float* __restrict__ x, float* __restrict__ out, int B)
{
    __shared__ __align__(16) float2 sp[4][32];   // [warp][lane] s partial
    __shared__ __align__(16) float  se[64];      // exp(logits), unnormalized

    const int t = threadIdx.x;
    const int w = t >> 5, l = t & 31;
    const int stride = gridDim.x;

    // butterfly output row: rA4 = bitrev4(l & 15); myrow = 16w + rA4
    const int rA4 = ((l & 1) << 3) | ((l & 2) << 1) | ((l & 4) >> 1) | ((l & 8) >> 3);
    const int myrow = 16 * w + rA4;

    for (int b = blockIdx.x; b < B; b += stride) {
        const float* __restrict__ xb = x + (size_t)b * 4096 + w * 1024 + 2 * l;

        // ---- load this warp's 16 rows: 16 coalesced LDG.64 per lane ----
        float2 xc[16];
#pragma unroll
        for (int n = 0; n < 16; n++)
            xc[n] = *reinterpret_cast<const float2*>(xb + n * 64);

        // ---- prefetch next batch into L2 (128B per thread = full 16KB) ----
        {
            const int bn = b + stride;
            if (bn < B) {
                const char* pf = (const char*)(x + (size_t)bn * 4096) + t * 128;
                asm volatile("prefetch.global.L2 [%0];" :: "l"(pf));
            }
        }

        float blog = 0.f;                    // logit for row myrow

#pragma unroll
        for (int it = 0; it < 3; it++) {
            // ---- s-phase partial over own 16 rows + zinv ----
            float p0, p1, zinv;
            if (it == 0) {
                float a0 = 0.f, a1 = 0.f, c0 = 0.f, c1 = 0.f;
#pragma unroll
                for (int n = 0; n < 16; n += 2) {
                    a0 += xc[n].x;     a1 += xc[n].y;
                    c0 += xc[n + 1].x; c1 += xc[n + 1].y;
                }
                p0 = a0 + c0; p1 = a1 + c1;
                zinv = 1.0f / 64.0f;         // softmax(0) = 1/64
            } else {
                float zl = se[l] + se[l + 32];
#pragma unroll
                for (int off = 16; off > 0; off >>= 1)
                    zl += __shfl_xor_sync(FULLMASK, zl, off);
                zinv = frcp(zl);
                float u0 = 0.f, u1 = 0.f, v0 = 0.f, v1 = 0.f;
                const float4* __restrict__ c4 =
                    reinterpret_cast<const float4*>(&se[16 * w]);
#pragma unroll
                for (int m = 0; m < 4; m++) {
                    float4 c = c4[m];        // broadcast LDS.128
                    u0 = fmaf(c.x, xc[4 * m].x, u0);     u1 = fmaf(c.x, xc[4 * m].y, u1);
                    v0 = fmaf(c.y, xc[4 * m + 1].x, v0); v1 = fmaf(c.y, xc[4 * m + 1].y, v1);
                    u0 = fmaf(c.z, xc[4 * m + 2].x, u0); u1 = fmaf(c.z, xc[4 * m + 2].y, u1);
                    v0 = fmaf(c.w, xc[4 * m + 3].x, v0); v1 = fmaf(c.w, xc[4 * m + 3].y, v1);
                }
                p0 = u0 + v0; p1 = u1 + v1;
            }
            sp[w][l] = make_float2(p0, p1);
            __syncthreads();                 // barrier 1: partials ready

            // ---- combine 4 partials (redundant in every warp) ----
            float2 a0 = sp[0][l], a1 = sp[1][l], a2 = sp[2][l], a3 = sp[3][l];
            float s0 = ((a0.x + a1.x) + (a2.x + a3.x)) * zinv;
            float s1 = ((a0.y + a1.y) + (a2.y + a3.y)) * zinv;

            // ---- squash scale (shuffle-only, redundant per warp) ----
            float nq = s0 * s0 + s1 * s1;
#pragma unroll
            for (int off = 16; off > 0; off >>= 1)
                nq += __shfl_xor_sync(FULLMASK, nq, off);
            const float rn    = frsq(nq + 1e-20f);
            const float nrm   = nq * rn;
            const float scale = nq * frcp((1.0f + nq) * (nrm + 1e-8f));

            if (it == 2) {                   // ---- final write (warp 0) ----
                if (w == 0)
                    *reinterpret_cast<float2*>(out + (size_t)b * 64 + 2 * l) =
                        make_float2(s0 * scale, s1 * scale);
                break;
            }

            // ---- agreement: intra-warp butterfly over own 16 rows ----
            float red[8];
            {
                const bool hi = l & 1;
#pragma unroll
                for (int i = 0; i < 8; i++) {
                    float ta = fmaf(xc[i].y,     s1, xc[i].x     * s0);
                    float tb = fmaf(xc[i + 8].y, s1, xc[i + 8].x * s0);
                    float send = hi ? ta : tb;
                    float recv = __shfl_xor_sync(FULLMASK, send, 1);
                    red[i] = (hi ? tb : ta) + recv;
                }
            }
#pragma unroll
            for (int k = 1; k < 4; k++) {
                const int half = 8 >> k;
                const bool hb = (l >> k) & 1;
#pragma unroll
                for (int i = 0; i < half; i++) {
                    float send = hb ? red[i] : red[i + half];
                    float recv = __shfl_xor_sync(FULLMASK, send, 1 << k);
                    red[i] = (hb ? red[i + half] : red[i]) + recv;
                }
            }
            // red[0]: partial over this 16-lane half; complete across halves
            red[0] += __shfl_xor_sync(FULLMASK, red[0], 16);
            blog += red[0] * scale;          // full dot for row myrow
            if (l < 16) se[myrow] = __expf(blog);
            __syncthreads();                 // barrier 2: se visible; WARs
        }

        __syncthreads();                     // batch-end: fence last sp read
                                             // vs next batch's sp write
    }
}

extern "C" void kernel_launch(void* const* d_in, const int* in_sizes, int n_in,
                              void* d_out, int out_size)
{
    const float* x = (const float*)d_in[0];
    float* out = (float*)d_out;
    const int B = in_sizes[0] / 4096;
    int grid = 148 * 7;                // persistent: 7 CTAs/SM
    if (grid > B) grid = B;
    routing_kernel<<<grid, 128>>>(x, out, B);
}